// round 1
// baseline (speedup 1.0000x reference)
#include <cuda_runtime.h>
#include <math.h>

// ---------------- problem constants ----------------
#define NB 2
#define CC 256
#define HH 100
#define WW 100
#define NROI 512
#define PP 7
#define SS 4
#define SCALEF 0.0625f
#define TRANS_STDF 0.1f
#define K1 (CC*PP*PP)     // 12544
#define DFC 1024
#define M3 (PP*PP*3)      // 147
#define NBIN (NROI*PP*PP) // 25088

// ---------------- scratch (device globals; no allocs allowed) ----------------
__device__ float g_featT[NB*HH*WW*CC];   // NHWC features
__device__ float g_X[NROI*K1];           // pooled (no-trans) features, (N, C*49)
__device__ float g_H1[NROI*DFC];
__device__ float g_H2[NROI*DFC];
__device__ float g_OM[NROI*M3];          // offsets (2*49) + mask logit (49)

// ---------------- NCHW -> NHWC transpose ----------------
__global__ void transpose_kernel(const float* __restrict__ feat) {
    __shared__ float tile[32][33];
    int b   = blockIdx.z;
    int hw0 = blockIdx.x * 32;
    int c0  = blockIdx.y * 32;
    int tx = threadIdx.x, ty = threadIdx.y; // (32, 8)
    const float* src = feat + (size_t)b * CC * HH * WW;
    float* dst = g_featT + (size_t)b * HH * WW * CC;
    #pragma unroll
    for (int j = 0; j < 32; j += 8) {
        int c  = c0 + ty + j;
        int hw = hw0 + tx;
        tile[ty + j][tx] = (hw < HH*WW) ? src[c * (HH*WW) + hw] : 0.0f;
    }
    __syncthreads();
    #pragma unroll
    for (int j = 0; j < 32; j += 8) {
        int hw = hw0 + ty + j;
        int c  = c0 + tx;
        if (hw < HH*WW) dst[hw * CC + c] = tile[tx][ty + j];
    }
}

// ---------------- deformable PSROI pool (group_size=1) ----------------
// One block per (roi, bin). Thread 0 builds a deduped 6x6 bilinear-weight grid
// (bin sample span <= ~2.7 px since roi_w <= 25.2), then 256 threads (one per
// channel) gather the few nonzero grid cells from NHWC features (coalesced).
template<bool TRANS>
__global__ void pool_kernel(const float* __restrict__ rois, float* __restrict__ outp) {
    __shared__ float wgrid[36];
    __shared__ float s_cnt, s_mask;
    __shared__ int s_horg, s_worg, s_base;

    int bin = blockIdx.x;
    int n  = bin / 49;
    int pp = bin % 49;
    int tid = threadIdx.x;

    if (tid == 0) {
        #pragma unroll
        for (int i = 0; i < 36; i++) wgrid[i] = 0.0f;
        int ph = pp / 7, pw = pp % 7;
        const float* r = rois + n * 5;
        int b = (int)r[0];
        float rsw = rintf(r[1]) * SCALEF - 0.5f;
        float rsh = rintf(r[2]) * SCALEF - 0.5f;
        float rew = (rintf(r[3]) + 1.0f) * SCALEF - 0.5f;
        float reh = (rintf(r[4]) + 1.0f) * SCALEF - 0.5f;
        float roi_w = fmaxf(rew - rsw, 0.1f);
        float roi_h = fmaxf(reh - rsh, 0.1f);
        float bin_h = roi_h / (float)PP;
        float bin_w = roi_w / (float)PP;
        float sub_h = bin_h / (float)SS;
        float sub_w = bin_w / (float)SS;

        float tx_ = 0.0f, ty_ = 0.0f, mask = 1.0f;
        if (TRANS) {
            // replicate reference float math exactly for part indices
            int part_h = (int)floorf((float)ph / (float)PP * 7.0f);
            int part_w = (int)floorf((float)pw / (float)PP * 7.0f);
            const float* o = g_OM + n * M3;
            tx_ = o[0*49 + part_h*7 + part_w] * TRANS_STDF;
            ty_ = o[1*49 + part_h*7 + part_w] * TRANS_STDF;
            float ml = o[2*49 + pp];
            mask = 1.0f / (1.0f + expf(-ml));
        }
        float hstart = (float)ph * bin_h + rsh + ty_ * roi_h;
        float wstart = (float)pw * bin_w + rsw + tx_ * roi_w;

        int horg = (int)floorf(fminf(fmaxf(hstart, 0.0f), (float)(HH-1)));
        int worg = (int)floorf(fminf(fmaxf(wstart, 0.0f), (float)(WW-1)));
        int cnt = 0;
        #pragma unroll
        for (int iy = 0; iy < SS; iy++) {
            float h = hstart + (float)iy * sub_h;
            #pragma unroll
            for (int ix = 0; ix < SS; ix++) {
                float w = wstart + (float)ix * sub_w;
                bool valid = (w >= -0.5f) && (w <= (float)WW - 0.5f) &&
                             (h >= -0.5f) && (h <= (float)HH - 0.5f);
                if (!valid) continue;
                cnt++;
                float hc = fminf(fmaxf(h, 0.0f), (float)(HH-1));
                float wc = fminf(fmaxf(w, 0.0f), (float)(WW-1));
                int h0 = (int)floorf(hc), w0 = (int)floorf(wc);
                int h1 = min(h0 + 1, HH - 1), w1 = min(w0 + 1, WW - 1);
                float lh = hc - (float)h0, lw = wc - (float)w0;
                int r0 = min(max(h0 - horg, 0), 5);
                int r1 = min(max(h1 - horg, 0), 5);
                int c0 = min(max(w0 - worg, 0), 5);
                int c1 = min(max(w1 - worg, 0), 5);
                wgrid[r0*6 + c0] += (1.0f - lh) * (1.0f - lw);
                wgrid[r0*6 + c1] += (1.0f - lh) * lw;
                wgrid[r1*6 + c0] += lh * (1.0f - lw);
                wgrid[r1*6 + c1] += lh * lw;
            }
        }
        s_cnt  = (float)cnt;
        s_mask = mask;
        s_horg = horg; s_worg = worg;
        s_base = b * HH * WW * CC;
    }
    __syncthreads();

    int c = tid;               // 256 threads == CC channels
    int base = s_base;
    int horg = s_horg, worg = s_worg;
    float acc = 0.0f;
    #pragma unroll
    for (int cell = 0; cell < 36; cell++) {
        float wt = wgrid[cell];
        if (wt != 0.0f) {
            int y = min(horg + cell / 6, HH - 1);
            int x = min(worg + cell % 6, WW - 1);
            acc += wt * g_featT[base + (y * WW + x) * CC + c];
        }
    }
    float cnt = s_cnt;
    float v = (cnt > 0.0f) ? (acc / cnt) : 0.0f;
    if (TRANS) {
        outp[(size_t)n * K1 + c * 49 + pp] = v * s_mask; // (N,C,P,P) layout
    } else {
        g_X[(size_t)n * K1 + c * 49 + pp] = v;
    }
}

// ---------------- fp32 SIMT GEMM: C[i,j] = act(sum_k A[i,k]*W[j,k] + b[j]) ----------------
// 64x64 tile, 256 threads, 4x4 micro-tile, BK=16, register prefetch of next tile.
template<int LAYER>
__global__ void __launch_bounds__(256) fc_kernel(const float* __restrict__ Wt,
                                                 const float* __restrict__ bias) {
    constexpr int K    = (LAYER == 1) ? K1 : DFC;
    constexpr int J    = (LAYER == 3) ? M3 : DFC;
    constexpr bool RELU = (LAYER != 3);

    const float* A    = (LAYER == 1) ? g_X  : (LAYER == 2 ? g_H1 : g_H2);
    float*       Cout = (LAYER == 1) ? g_H1 : (LAYER == 2 ? g_H2 : g_OM);

    __shared__ __align__(16) float As[16][68];
    __shared__ __align__(16) float Bs[16][68];

    int tid = threadIdx.x;
    int tx = tid & 15;
    int ty = tid >> 4;
    int j0 = blockIdx.x * 64;
    int i0 = blockIdx.y * 64;

    int lr = tid >> 2;   // 0..63 : row within tile
    int lq = tid & 3;    // 0..3  : float4 slot within BK=16

    int arow = i0 + lr;                 // always < 512
    int brow = j0 + lr;
    bool bok = brow < J;
    const float* Aptr = A + (size_t)arow * K + lq * 4;
    const float* Bptr = Wt + (size_t)(bok ? brow : 0) * K + lq * 4;

    float acc[4][4];
    #pragma unroll
    for (int u = 0; u < 4; u++)
        #pragma unroll
        for (int v = 0; v < 4; v++) acc[u][v] = 0.0f;

    float4 af = *reinterpret_cast<const float4*>(Aptr);
    float4 bf = bok ? *reinterpret_cast<const float4*>(Bptr)
                    : make_float4(0.f, 0.f, 0.f, 0.f);

    #pragma unroll 1
    for (int kt = 0; kt < K; kt += 16) {
        As[lq*4 + 0][lr] = af.x; As[lq*4 + 1][lr] = af.y;
        As[lq*4 + 2][lr] = af.z; As[lq*4 + 3][lr] = af.w;
        Bs[lq*4 + 0][lr] = bf.x; Bs[lq*4 + 1][lr] = bf.y;
        Bs[lq*4 + 2][lr] = bf.z; Bs[lq*4 + 3][lr] = bf.w;
        __syncthreads();

        if (kt + 16 < K) {
            af = *reinterpret_cast<const float4*>(Aptr + kt + 16);
            bf = bok ? *reinterpret_cast<const float4*>(Bptr + kt + 16)
                     : make_float4(0.f, 0.f, 0.f, 0.f);
        }

        #pragma unroll
        for (int kk = 0; kk < 16; kk++) {
            float4 a = *reinterpret_cast<const float4*>(&As[kk][ty * 4]);
            float4 b = *reinterpret_cast<const float4*>(&Bs[kk][tx * 4]);
            float av[4] = {a.x, a.y, a.z, a.w};
            float bv[4] = {b.x, b.y, b.z, b.w};
            #pragma unroll
            for (int u = 0; u < 4; u++)
                #pragma unroll
                for (int v = 0; v < 4; v++)
                    acc[u][v] = fmaf(av[u], bv[v], acc[u][v]);
        }
        __syncthreads();
    }

    int irow = i0 + ty * 4;
    int jcol = j0 + tx * 4;
    #pragma unroll
    for (int u = 0; u < 4; u++) {
        #pragma unroll
        for (int v = 0; v < 4; v++) {
            int j = jcol + v;
            if (j < J) {
                float val = acc[u][v] + bias[j];
                if (RELU) val = fmaxf(val, 0.0f);
                Cout[(size_t)(irow + u) * J + j] = val;
            }
        }
    }
}

// ---------------- launch ----------------
extern "C" void kernel_launch(void* const* d_in, const int* in_sizes, int n_in,
                              void* d_out, int out_size) {
    const float* feat = (const float*)d_in[0];
    const float* rois = (const float*)d_in[1];
    const float* w1   = (const float*)d_in[2];
    const float* b1   = (const float*)d_in[3];
    const float* w2   = (const float*)d_in[4];
    const float* b2   = (const float*)d_in[5];
    const float* w3   = (const float*)d_in[6];
    const float* b3   = (const float*)d_in[7];
    float* out = (float*)d_out;

    // 1. NCHW -> NHWC
    dim3 tb(32, 8);
    dim3 tg((HH*WW + 31) / 32, CC / 32, NB);
    transpose_kernel<<<tg, tb>>>(feat);

    // 2. pool without offsets -> g_X
    pool_kernel<false><<<NBIN, 256>>>(rois, nullptr);

    // 3. FC stack
    fc_kernel<1><<<dim3(DFC/64, NROI/64), 256>>>(w1, b1);
    fc_kernel<2><<<dim3(DFC/64, NROI/64), 256>>>(w2, b2);
    fc_kernel<3><<<dim3((M3 + 63)/64, NROI/64), 256>>>(w3, b3);

    // 4. deformable pool with offsets, times sigmoid mask -> out
    pool_kernel<true><<<NBIN, 256>>>(rois, out);
}

// round 3
// speedup vs baseline: 2.3852x; 2.3852x over previous
#include <cuda_runtime.h>
#include <math.h>
#include <stdint.h>

// ---------------- problem constants ----------------
#define NB 2
#define CC 256
#define HH 100
#define WW 100
#define NROI 512
#define PP 7
#define SS 4
#define SCALEF 0.0625f
#define TRANS_STDF 0.1f
#define K1 (CC*PP*PP)     // 12544
#define DFC 1024
#define M3 (PP*PP*3)      // 147
#define NBIN (NROI*PP*PP) // 25088

// ---------------- scratch (device globals; no allocs allowed) ----------------
__device__ float g_featT[NB*HH*WW*CC];   // NHWC features
__device__ float g_X[NROI*K1];           // pooled (no-trans) features
__device__ float g_H1[NROI*DFC];
__device__ float g_H2[NROI*DFC];
__device__ float g_OM[NROI*M3];          // offsets (2*49) + mask logit (49)

// ======================= small PTX helpers (sm_80+ baseline only) =======================
__device__ __forceinline__ uint32_t smem_u32(const void* p) {
    uint32_t a;
    asm("{ .reg .u64 t; cvta.to.shared.u64 t, %1; cvt.u32.u64 %0, t; }"
        : "=r"(a) : "l"(p));
    return a;
}

__device__ __forceinline__ void cpasync16(uint32_t dst, const void* src, bool pred) {
    int sz = pred ? 16 : 0;
    asm volatile("cp.async.cg.shared.global [%0], [%1], 16, %2;"
                 :: "r"(dst), "l"(src), "r"(sz) : "memory");
}

__device__ __forceinline__ uint32_t f2tf32(float f) {
    uint32_t u;
    asm("cvt.rna.tf32.f32 %0, %1;" : "=r"(u) : "f"(f));
    return u;
}

__device__ __forceinline__ void mma_tf32(float c[4], const uint32_t a[4], const uint32_t b[2]) {
    asm volatile(
        "mma.sync.aligned.m16n8k8.row.col.f32.tf32.tf32.f32 "
        "{%0,%1,%2,%3}, {%4,%5,%6,%7}, {%8,%9}, {%0,%1,%2,%3};"
        : "+f"(c[0]), "+f"(c[1]), "+f"(c[2]), "+f"(c[3])
        : "r"(a[0]), "r"(a[1]), "r"(a[2]), "r"(a[3]), "r"(b[0]), "r"(b[1]));
}

// ---------------- NCHW -> NHWC transpose ----------------
__global__ void transpose_kernel(const float* __restrict__ feat) {
    __shared__ float tile[32][33];
    int b   = blockIdx.z;
    int hw0 = blockIdx.x * 32;
    int c0  = blockIdx.y * 32;
    int tx = threadIdx.x, ty = threadIdx.y; // (32, 8)
    const float* src = feat + (size_t)b * CC * HH * WW;
    float* dst = g_featT + (size_t)b * HH * WW * CC;
    #pragma unroll
    for (int j = 0; j < 32; j += 8) {
        int c  = c0 + ty + j;
        int hw = hw0 + tx;
        tile[ty + j][tx] = (hw < HH*WW) ? src[c * (HH*WW) + hw] : 0.0f;
    }
    __syncthreads();
    #pragma unroll
    for (int j = 0; j < 32; j += 8) {
        int hw = hw0 + ty + j;
        int c  = c0 + tx;
        if (hw < HH*WW) dst[hw * CC + c] = tile[tx][ty + j];
    }
}

// ---------------- deformable PSROI pool (group_size=1) ----------------
template<bool TRANS>
__global__ void pool_kernel(const float* __restrict__ rois, float* __restrict__ outp) {
    __shared__ float wgrid[36];
    __shared__ float s_cnt, s_mask;
    __shared__ int s_horg, s_worg, s_base;

    int bin = blockIdx.x;
    int n  = bin / 49;
    int pp = bin % 49;
    int tid = threadIdx.x;

    if (tid == 0) {
        #pragma unroll
        for (int i = 0; i < 36; i++) wgrid[i] = 0.0f;
        int ph = pp / 7, pw = pp % 7;
        const float* r = rois + n * 5;
        int b = (int)r[0];
        float rsw = rintf(r[1]) * SCALEF - 0.5f;
        float rsh = rintf(r[2]) * SCALEF - 0.5f;
        float rew = (rintf(r[3]) + 1.0f) * SCALEF - 0.5f;
        float reh = (rintf(r[4]) + 1.0f) * SCALEF - 0.5f;
        float roi_w = fmaxf(rew - rsw, 0.1f);
        float roi_h = fmaxf(reh - rsh, 0.1f);
        float bin_h = roi_h / (float)PP;
        float bin_w = roi_w / (float)PP;
        float sub_h = bin_h / (float)SS;
        float sub_w = bin_w / (float)SS;

        float tx_ = 0.0f, ty_ = 0.0f, mask = 1.0f;
        if (TRANS) {
            int part_h = (int)floorf((float)ph / (float)PP * 7.0f);
            int part_w = (int)floorf((float)pw / (float)PP * 7.0f);
            const float* o = g_OM + n * M3;
            tx_ = o[0*49 + part_h*7 + part_w] * TRANS_STDF;
            ty_ = o[1*49 + part_h*7 + part_w] * TRANS_STDF;
            float ml = o[2*49 + pp];
            mask = 1.0f / (1.0f + expf(-ml));
        }
        float hstart = (float)ph * bin_h + rsh + ty_ * roi_h;
        float wstart = (float)pw * bin_w + rsw + tx_ * roi_w;

        int horg = (int)floorf(fminf(fmaxf(hstart, 0.0f), (float)(HH-1)));
        int worg = (int)floorf(fminf(fmaxf(wstart, 0.0f), (float)(WW-1)));
        int cnt = 0;
        #pragma unroll
        for (int iy = 0; iy < SS; iy++) {
            float h = hstart + (float)iy * sub_h;
            #pragma unroll
            for (int ix = 0; ix < SS; ix++) {
                float w = wstart + (float)ix * sub_w;
                bool valid = (w >= -0.5f) && (w <= (float)WW - 0.5f) &&
                             (h >= -0.5f) && (h <= (float)HH - 0.5f);
                if (!valid) continue;
                cnt++;
                float hc = fminf(fmaxf(h, 0.0f), (float)(HH-1));
                float wc = fminf(fmaxf(w, 0.0f), (float)(WW-1));
                int h0 = (int)floorf(hc), w0 = (int)floorf(wc);
                int h1 = min(h0 + 1, HH - 1), w1 = min(w0 + 1, WW - 1);
                float lh = hc - (float)h0, lw = wc - (float)w0;
                int r0 = min(max(h0 - horg, 0), 5);
                int r1 = min(max(h1 - horg, 0), 5);
                int c0 = min(max(w0 - worg, 0), 5);
                int c1 = min(max(w1 - worg, 0), 5);
                wgrid[r0*6 + c0] += (1.0f - lh) * (1.0f - lw);
                wgrid[r0*6 + c1] += (1.0f - lh) * lw;
                wgrid[r1*6 + c0] += lh * (1.0f - lw);
                wgrid[r1*6 + c1] += lh * lw;
            }
        }
        s_cnt  = (float)cnt;
        s_mask = mask;
        s_horg = horg; s_worg = worg;
        s_base = b * HH * WW * CC;
    }
    __syncthreads();

    int c = tid;               // 256 threads == CC channels
    int base = s_base;
    int horg = s_horg, worg = s_worg;
    float acc = 0.0f;
    #pragma unroll
    for (int cell = 0; cell < 36; cell++) {
        float wt = wgrid[cell];
        if (wt != 0.0f) {
            int y = min(horg + cell / 6, HH - 1);
            int x = min(worg + cell % 6, WW - 1);
            acc += wt * g_featT[base + (y * WW + x) * CC + c];
        }
    }
    float cnt = s_cnt;
    float v = (cnt > 0.0f) ? (acc / cnt) : 0.0f;
    if (TRANS) {
        outp[(size_t)n * K1 + c * 49 + pp] = v * s_mask;
    } else {
        g_X[(size_t)n * K1 + c * 49 + pp] = v;
    }
}

// ============ TF32 mma.sync GEMM: C[i,j] = act(sum_k A[i,k]*W[j,k] + bias[j]) ============
// BM=BN=64, BK=32, 4 warps (32x32 warp tiles), 4-stage cp.async pipeline.
#define BM 64
#define BN 64
#define BK 32
#define GPAD 36                      // floats per smem row (conflict-free frag loads)
#define GSTAGES 4
#define ASZ (BM*GPAD)
#define BSZ (BN*GPAD)
#define STGSZ (ASZ+BSZ)
#define GEMM_SMEM_BYTES (GSTAGES*STGSZ*4)

template<int KDIM, int J, bool RELU>
__global__ void __launch_bounds__(128, 1) fcmma_kernel(
    const float* __restrict__ A, const float* __restrict__ Wt,
    const float* __restrict__ bias, float* __restrict__ Cout)
{
    static_assert(KDIM % BK == 0, "K multiple of BK");
    constexpr int KT = KDIM / BK;

    extern __shared__ float sm[];
    int tid  = threadIdx.x;
    int lane = tid & 31, wid = tid >> 5;
    int m0 = blockIdx.y * BM, n0 = blockIdx.x * BN;

    int g = lane >> 2, tg = lane & 3;
    int wm = (wid & 1) * 32, wn = (wid >> 1) * 32;

    float c[2][4][4];
    #pragma unroll
    for (int mt = 0; mt < 2; mt++)
        #pragma unroll
        for (int nt = 0; nt < 4; nt++)
            #pragma unroll
            for (int q = 0; q < 4; q++) c[mt][nt][q] = 0.0f;

    int lrow = tid >> 3;     // 0..15
    int lchk = tid & 7;      // 0..7 (16B chunks of a 128B row)

    auto load_stage = [&](int s, int t) {
        float* As = sm + s * STGSZ;
        float* Bs = As + ASZ;
        int kg = t * BK + lchk * 4;
        #pragma unroll
        for (int it = 0; it < 4; it++) {
            int r = lrow + it * 16;
            cpasync16(smem_u32(As + r * GPAD + lchk * 4),
                      A + (size_t)(m0 + r) * KDIM + kg, true);
            int br = n0 + r;
            bool ok = ((J % BN) == 0) || (br < J);
            cpasync16(smem_u32(Bs + r * GPAD + lchk * 4),
                      Wt + (size_t)(ok ? br : 0) * KDIM + kg, ok);
        }
    };

    // prologue: stages 0..GSTAGES-2
    #pragma unroll
    for (int s = 0; s < GSTAGES - 1; s++) {
        if (s < KT) load_stage(s, s);
        asm volatile("cp.async.commit_group;" ::: "memory");
    }

    #pragma unroll 1
    for (int t = 0; t < KT; t++) {
        asm volatile("cp.async.wait_group %0;" :: "n"(GSTAGES - 2) : "memory");
        __syncthreads();

        int tn = t + GSTAGES - 1;
        if (tn < KT) load_stage(tn % GSTAGES, tn);
        asm volatile("cp.async.commit_group;" ::: "memory");

        const float* As = sm + (t % GSTAGES) * STGSZ;
        const float* Bs = As + ASZ;
        #pragma unroll
        for (int ks = 0; ks < 4; ks++) {
            int kk = ks * 8;
            uint32_t a[2][4], b[4][2];
            #pragma unroll
            for (int mt = 0; mt < 2; mt++) {
                int m = wm + mt * 16 + g;
                a[mt][0] = f2tf32(As[m * GPAD + kk + tg]);
                a[mt][1] = f2tf32(As[(m + 8) * GPAD + kk + tg]);
                a[mt][2] = f2tf32(As[m * GPAD + kk + tg + 4]);
                a[mt][3] = f2tf32(As[(m + 8) * GPAD + kk + tg + 4]);
            }
            #pragma unroll
            for (int nt = 0; nt < 4; nt++) {
                int nn = wn + nt * 8 + g;
                b[nt][0] = f2tf32(Bs[nn * GPAD + kk + tg]);
                b[nt][1] = f2tf32(Bs[nn * GPAD + kk + tg + 4]);
            }
            #pragma unroll
            for (int mt = 0; mt < 2; mt++)
                #pragma unroll
                for (int nt = 0; nt < 4; nt++)
                    mma_tf32(c[mt][nt], a[mt], b[nt]);
        }
    }

    // epilogue: bias + activation, direct global stores
    #pragma unroll
    for (int mt = 0; mt < 2; mt++) {
        int row0 = m0 + wm + mt * 16 + g;
        #pragma unroll
        for (int nt = 0; nt < 4; nt++) {
            int j0 = n0 + wn + nt * 8 + tg * 2;
            #pragma unroll
            for (int q = 0; q < 4; q++) {
                int row = row0 + (q >> 1) * 8;
                int j   = j0 + (q & 1);
                if (((J % BN) == 0) || (j < J)) {
                    float v = c[mt][nt][q] + bias[j];
                    if (RELU) v = fmaxf(v, 0.0f);
                    Cout[(size_t)row * J + j] = v;
                }
            }
        }
    }
}

// ======================= launch =======================
extern "C" void kernel_launch(void* const* d_in, const int* in_sizes, int n_in,
                              void* d_out, int out_size) {
    const float* feat = (const float*)d_in[0];
    const float* rois = (const float*)d_in[1];
    const float* w1   = (const float*)d_in[2];
    const float* b1   = (const float*)d_in[3];
    const float* w2   = (const float*)d_in[4];
    const float* b2   = (const float*)d_in[5];
    const float* w3   = (const float*)d_in[6];
    const float* b3   = (const float*)d_in[7];
    float* out = (float*)d_out;

    static float *pX = nullptr, *pH1 = nullptr, *pH2 = nullptr, *pOM = nullptr;
    if (!pX) {
        void* p;
        cudaGetSymbolAddress(&p, g_X);  pX  = (float*)p;
        cudaGetSymbolAddress(&p, g_H1); pH1 = (float*)p;
        cudaGetSymbolAddress(&p, g_H2); pH2 = (float*)p;
        cudaGetSymbolAddress(&p, g_OM); pOM = (float*)p;
        cudaFuncSetAttribute(fcmma_kernel<K1,  DFC, true>,
                             cudaFuncAttributeMaxDynamicSharedMemorySize, GEMM_SMEM_BYTES);
        cudaFuncSetAttribute(fcmma_kernel<DFC, DFC, true>,
                             cudaFuncAttributeMaxDynamicSharedMemorySize, GEMM_SMEM_BYTES);
        cudaFuncSetAttribute(fcmma_kernel<DFC, M3,  false>,
                             cudaFuncAttributeMaxDynamicSharedMemorySize, GEMM_SMEM_BYTES);
    }

    // 1. NCHW -> NHWC
    dim3 tb(32, 8);
    dim3 tg((HH*WW + 31) / 32, CC / 32, NB);
    transpose_kernel<<<tg, tb>>>(feat);

    // 2. pool without offsets -> g_X
    pool_kernel<false><<<NBIN, 256>>>(rois, nullptr);

    // 3. FC stack on TF32 mma.sync
    fcmma_kernel<K1,  DFC, true><<<dim3(DFC/BN, NROI/BM), 128, GEMM_SMEM_BYTES>>>(pX,  w1, b1, pH1);
    fcmma_kernel<DFC, DFC, true><<<dim3(DFC/BN, NROI/BM), 128, GEMM_SMEM_BYTES>>>(pH1, w2, b2, pH2);
    fcmma_kernel<DFC, M3, false><<<dim3((M3+BN-1)/BN, NROI/BM), 128, GEMM_SMEM_BYTES>>>(pH2, w3, b3, pOM);

    // 4. deformable pool with offsets, times sigmoid mask -> out
    pool_kernel<true><<<NBIN, 256>>>(rois, out);
}

// round 4
// speedup vs baseline: 2.6962x; 1.1304x over previous
#include <cuda_runtime.h>
#include <math.h>
#include <stdint.h>

// ---------------- problem constants ----------------
#define NB 2
#define CC 256
#define HH 100
#define WW 100
#define NROI 512
#define PP 7
#define SS 4
#define SCALEF 0.0625f
#define TRANS_STDF 0.1f
#define K1 (CC*PP*PP)     // 12544
#define DFC 1024
#define M3 (PP*PP*3)      // 147
#define NBIN (NROI*PP*PP) // 25088

// ---------------- scratch (device globals; no allocs allowed) ----------------
__device__ float g_featT[NB*HH*WW*CC];   // NHWC features
__device__ float g_X[NROI*K1];           // pooled (no-trans) features
__device__ float g_H1[NROI*DFC];
__device__ float g_H2[NROI*DFC];
__device__ float g_OM[NROI*M3];          // offsets (2*49) + mask logit (49)
__device__ float g_part[4*NROI*DFC];     // split-K partials (8 MB, reused per layer)

// ======================= small PTX helpers (sm_80+ baseline only) =======================
__device__ __forceinline__ uint32_t smem_u32(const void* p) {
    uint32_t a;
    asm("{ .reg .u64 t; cvta.to.shared.u64 t, %1; cvt.u32.u64 %0, t; }"
        : "=r"(a) : "l"(p));
    return a;
}

__device__ __forceinline__ void cpasync16(uint32_t dst, const void* src, bool pred) {
    int sz = pred ? 16 : 0;
    asm volatile("cp.async.cg.shared.global [%0], [%1], 16, %2;"
                 :: "r"(dst), "l"(src), "r"(sz) : "memory");
}

__device__ __forceinline__ uint32_t f2tf32(float f) {
    uint32_t u;
    asm("cvt.rna.tf32.f32 %0, %1;" : "=r"(u) : "f"(f));
    return u;
}

__device__ __forceinline__ void mma_tf32(float c[4], const uint32_t a[4], const uint32_t b[2]) {
    asm volatile(
        "mma.sync.aligned.m16n8k8.row.col.f32.tf32.tf32.f32 "
        "{%0,%1,%2,%3}, {%4,%5,%6,%7}, {%8,%9}, {%0,%1,%2,%3};"
        : "+f"(c[0]), "+f"(c[1]), "+f"(c[2]), "+f"(c[3])
        : "r"(a[0]), "r"(a[1]), "r"(a[2]), "r"(a[3]), "r"(b[0]), "r"(b[1]));
}

// ---------------- NCHW -> NHWC transpose ----------------
__global__ void transpose_kernel(const float* __restrict__ feat) {
    __shared__ float tile[32][33];
    int b   = blockIdx.z;
    int hw0 = blockIdx.x * 32;
    int c0  = blockIdx.y * 32;
    int tx = threadIdx.x, ty = threadIdx.y; // (32, 8)
    const float* src = feat + (size_t)b * CC * HH * WW;
    float* dst = g_featT + (size_t)b * HH * WW * CC;
    #pragma unroll
    for (int j = 0; j < 32; j += 8) {
        int c  = c0 + ty + j;
        int hw = hw0 + tx;
        tile[ty + j][tx] = (hw < HH*WW) ? src[c * (HH*WW) + hw] : 0.0f;
    }
    __syncthreads();
    #pragma unroll
    for (int j = 0; j < 32; j += 8) {
        int hw = hw0 + ty + j;
        int c  = c0 + tx;
        if (hw < HH*WW) dst[hw * CC + c] = tile[tx][ty + j];
    }
}

// ---------------- deformable PSROI pool (group_size=1) ----------------
template<bool TRANS>
__global__ void pool_kernel(const float* __restrict__ rois, float* __restrict__ outp) {
    __shared__ float wgrid[36];
    __shared__ float s_cnt, s_mask;
    __shared__ int s_horg, s_worg, s_base;

    int bin = blockIdx.x;
    int n  = bin / 49;
    int pp = bin % 49;
    int tid = threadIdx.x;

    if (tid == 0) {
        #pragma unroll
        for (int i = 0; i < 36; i++) wgrid[i] = 0.0f;
        int ph = pp / 7, pw = pp % 7;
        const float* r = rois + n * 5;
        int b = (int)r[0];
        float rsw = rintf(r[1]) * SCALEF - 0.5f;
        float rsh = rintf(r[2]) * SCALEF - 0.5f;
        float rew = (rintf(r[3]) + 1.0f) * SCALEF - 0.5f;
        float reh = (rintf(r[4]) + 1.0f) * SCALEF - 0.5f;
        float roi_w = fmaxf(rew - rsw, 0.1f);
        float roi_h = fmaxf(reh - rsh, 0.1f);
        float bin_h = roi_h / (float)PP;
        float bin_w = roi_w / (float)PP;
        float sub_h = bin_h / (float)SS;
        float sub_w = bin_w / (float)SS;

        float tx_ = 0.0f, ty_ = 0.0f, mask = 1.0f;
        if (TRANS) {
            int part_h = (int)floorf((float)ph / (float)PP * 7.0f);
            int part_w = (int)floorf((float)pw / (float)PP * 7.0f);
            const float* o = g_OM + n * M3;
            tx_ = o[0*49 + part_h*7 + part_w] * TRANS_STDF;
            ty_ = o[1*49 + part_h*7 + part_w] * TRANS_STDF;
            float ml = o[2*49 + pp];
            mask = 1.0f / (1.0f + expf(-ml));
        }
        float hstart = (float)ph * bin_h + rsh + ty_ * roi_h;
        float wstart = (float)pw * bin_w + rsw + tx_ * roi_w;

        int horg = (int)floorf(fminf(fmaxf(hstart, 0.0f), (float)(HH-1)));
        int worg = (int)floorf(fminf(fmaxf(wstart, 0.0f), (float)(WW-1)));
        int cnt = 0;
        #pragma unroll
        for (int iy = 0; iy < SS; iy++) {
            float h = hstart + (float)iy * sub_h;
            #pragma unroll
            for (int ix = 0; ix < SS; ix++) {
                float w = wstart + (float)ix * sub_w;
                bool valid = (w >= -0.5f) && (w <= (float)WW - 0.5f) &&
                             (h >= -0.5f) && (h <= (float)HH - 0.5f);
                if (!valid) continue;
                cnt++;
                float hc = fminf(fmaxf(h, 0.0f), (float)(HH-1));
                float wc = fminf(fmaxf(w, 0.0f), (float)(WW-1));
                int h0 = (int)floorf(hc), w0 = (int)floorf(wc);
                int h1 = min(h0 + 1, HH - 1), w1 = min(w0 + 1, WW - 1);
                float lh = hc - (float)h0, lw = wc - (float)w0;
                int r0 = min(max(h0 - horg, 0), 5);
                int r1 = min(max(h1 - horg, 0), 5);
                int c0 = min(max(w0 - worg, 0), 5);
                int c1 = min(max(w1 - worg, 0), 5);
                wgrid[r0*6 + c0] += (1.0f - lh) * (1.0f - lw);
                wgrid[r0*6 + c1] += (1.0f - lh) * lw;
                wgrid[r1*6 + c0] += lh * (1.0f - lw);
                wgrid[r1*6 + c1] += lh * lw;
            }
        }
        s_cnt  = (float)cnt;
        s_mask = mask;
        s_horg = horg; s_worg = worg;
        s_base = b * HH * WW * CC;
    }
    __syncthreads();

    int c = tid;               // 256 threads == CC channels
    int base = s_base;
    int horg = s_horg, worg = s_worg;
    float acc = 0.0f;
    #pragma unroll
    for (int cell = 0; cell < 36; cell++) {
        float wt = wgrid[cell];
        if (wt != 0.0f) {
            int y = min(horg + cell / 6, HH - 1);
            int x = min(worg + cell % 6, WW - 1);
            acc += wt * g_featT[base + (y * WW + x) * CC + c];
        }
    }
    float cnt = s_cnt;
    float v = (cnt > 0.0f) ? (acc / cnt) : 0.0f;
    if (TRANS) {
        outp[(size_t)n * K1 + c * 49 + pp] = v * s_mask;
    } else {
        g_X[(size_t)n * K1 + c * 49 + pp] = v;
    }
}

// ============ TF32 mma.sync GEMM with split-K ============
// Part[z,i,j] = sum_{k in chunk z} A[i,k]*W[j,k].  BM=BN=64, BK=32, 4 warps,
// 3-stage cp.async pipeline. Reduce kernel folds partials + bias + act.
#define BM 64
#define BN 64
#define BK 32
#define GPAD 36
#define GSTAGES 3
#define ASZ (BM*GPAD)
#define BSZ (BN*GPAD)
#define STGSZ (ASZ+BSZ)
#define GEMM_SMEM_BYTES (GSTAGES*STGSZ*4)

template<int KDIM, int JROWS, int JS, int SPLITK>
__global__ void __launch_bounds__(128) fcmma_kernel(
    const float* __restrict__ A, const float* __restrict__ Wt,
    float* __restrict__ Part)
{
    static_assert(KDIM % BK == 0, "K multiple of BK");
    constexpr int KT = KDIM / BK;
    constexpr int CH = (KT + SPLITK - 1) / SPLITK;

    extern __shared__ float sm[];
    int tid  = threadIdx.x;
    int lane = tid & 31, wid = tid >> 5;
    int m0 = blockIdx.y * BM, n0 = blockIdx.x * BN;
    int z  = blockIdx.z;
    int t0 = z * CH;
    int ntc = min(KT - t0, CH);

    int g = lane >> 2, tg = lane & 3;
    int wm = (wid & 1) * 32, wn = (wid >> 1) * 32;

    float c[2][4][4];
    #pragma unroll
    for (int mt = 0; mt < 2; mt++)
        #pragma unroll
        for (int nt = 0; nt < 4; nt++)
            #pragma unroll
            for (int q = 0; q < 4; q++) c[mt][nt][q] = 0.0f;

    int lrow = tid >> 3;     // 0..15
    int lchk = tid & 7;      // 0..7 (16B chunks)

    auto load_stage = [&](int s, int t) {
        float* As = sm + s * STGSZ;
        float* Bs = As + ASZ;
        int kg = t * BK + lchk * 4;
        #pragma unroll
        for (int it = 0; it < 4; it++) {
            int r = lrow + it * 16;
            cpasync16(smem_u32(As + r * GPAD + lchk * 4),
                      A + (size_t)(m0 + r) * KDIM + kg, true);
            int br = n0 + r;
            bool ok = ((JROWS % BN) == 0) || (br < JROWS);
            cpasync16(smem_u32(Bs + r * GPAD + lchk * 4),
                      Wt + (size_t)(ok ? br : 0) * KDIM + kg, ok);
        }
    };

    #pragma unroll
    for (int s = 0; s < GSTAGES - 1; s++) {
        if (s < ntc) load_stage(s, t0 + s);
        asm volatile("cp.async.commit_group;" ::: "memory");
    }

    #pragma unroll 1
    for (int i = 0; i < ntc; i++) {
        asm volatile("cp.async.wait_group %0;" :: "n"(GSTAGES - 2) : "memory");
        __syncthreads();

        int tn = i + GSTAGES - 1;
        if (tn < ntc) load_stage(tn % GSTAGES, t0 + tn);
        asm volatile("cp.async.commit_group;" ::: "memory");

        const float* As = sm + (i % GSTAGES) * STGSZ;
        const float* Bs = As + ASZ;
        #pragma unroll
        for (int ks = 0; ks < 4; ks++) {
            int kk = ks * 8;
            uint32_t a[2][4], b[4][2];
            #pragma unroll
            for (int mt = 0; mt < 2; mt++) {
                int m = wm + mt * 16 + g;
                a[mt][0] = f2tf32(As[m * GPAD + kk + tg]);
                a[mt][1] = f2tf32(As[(m + 8) * GPAD + kk + tg]);
                a[mt][2] = f2tf32(As[m * GPAD + kk + tg + 4]);
                a[mt][3] = f2tf32(As[(m + 8) * GPAD + kk + tg + 4]);
            }
            #pragma unroll
            for (int nt = 0; nt < 4; nt++) {
                int nn = wn + nt * 8 + g;
                b[nt][0] = f2tf32(Bs[nn * GPAD + kk + tg]);
                b[nt][1] = f2tf32(Bs[nn * GPAD + kk + tg + 4]);
            }
            #pragma unroll
            for (int mt = 0; mt < 2; mt++)
                #pragma unroll
                for (int nt = 0; nt < 4; nt++)
                    mma_tf32(c[mt][nt], a[mt], b[nt]);
        }
        __syncthreads();
    }

    // write partials
    float* P = Part + (size_t)z * NROI * JS;
    #pragma unroll
    for (int mt = 0; mt < 2; mt++) {
        int row0 = m0 + wm + mt * 16 + g;
        #pragma unroll
        for (int nt = 0; nt < 4; nt++) {
            int j0 = n0 + wn + nt * 8 + tg * 2;
            #pragma unroll
            for (int h = 0; h < 2; h++) {
                int row = row0 + h * 8;
                float2 v = make_float2(c[mt][nt][h*2], c[mt][nt][h*2+1]);
                *reinterpret_cast<float2*>(P + (size_t)row * JS + j0) = v;
            }
        }
    }
}

template<int J, int JS, int SPLITK, bool RELU>
__global__ void __launch_bounds__(256) reduce_kernel(
    const float* __restrict__ Part, const float* __restrict__ bias,
    float* __restrict__ Cout)
{
    int idx = blockIdx.x * 256 + threadIdx.x;
    if (idx >= NROI * J) return;
    int row = idx / J, j = idx - row * J;
    float v = 0.0f;
    #pragma unroll
    for (int z = 0; z < SPLITK; z++)
        v += Part[((size_t)z * NROI + row) * JS + j];
    v += __ldg(bias + j);
    if (RELU) v = fmaxf(v, 0.0f);
    Cout[idx] = v;
}

// ======================= launch =======================
extern "C" void kernel_launch(void* const* d_in, const int* in_sizes, int n_in,
                              void* d_out, int out_size) {
    const float* feat = (const float*)d_in[0];
    const float* rois = (const float*)d_in[1];
    const float* w1   = (const float*)d_in[2];
    const float* b1   = (const float*)d_in[3];
    const float* w2   = (const float*)d_in[4];
    const float* b2   = (const float*)d_in[5];
    const float* w3   = (const float*)d_in[6];
    const float* b3   = (const float*)d_in[7];
    float* out = (float*)d_out;

    static float *pX=nullptr, *pH1=nullptr, *pH2=nullptr, *pOM=nullptr, *pPart=nullptr;
    if (!pX) {
        void* p;
        cudaGetSymbolAddress(&p, g_X);    pX    = (float*)p;
        cudaGetSymbolAddress(&p, g_H1);   pH1   = (float*)p;
        cudaGetSymbolAddress(&p, g_H2);   pH2   = (float*)p;
        cudaGetSymbolAddress(&p, g_OM);   pOM   = (float*)p;
        cudaGetSymbolAddress(&p, g_part); pPart = (float*)p;
        cudaFuncSetAttribute(fcmma_kernel<K1,  DFC, DFC, 4>,
                             cudaFuncAttributeMaxDynamicSharedMemorySize, GEMM_SMEM_BYTES);
        cudaFuncSetAttribute(fcmma_kernel<DFC, DFC, DFC, 3>,
                             cudaFuncAttributeMaxDynamicSharedMemorySize, GEMM_SMEM_BYTES);
        cudaFuncSetAttribute(fcmma_kernel<DFC, M3,  192, 6>,
                             cudaFuncAttributeMaxDynamicSharedMemorySize, GEMM_SMEM_BYTES);
    }

    // 1. NCHW -> NHWC
    dim3 tb(32, 8);
    dim3 tg((HH*WW + 31) / 32, CC / 32, NB);
    transpose_kernel<<<tg, tb>>>(feat);

    // 2. pool without offsets -> g_X
    pool_kernel<false><<<NBIN, 256>>>(rois, nullptr);

    // 3. FC stack: split-K TF32 mma.sync + reduce
    fcmma_kernel<K1,  DFC, DFC, 4><<<dim3(DFC/BN, NROI/BM, 4), 128, GEMM_SMEM_BYTES>>>(pX,  w1, pPart);
    reduce_kernel<DFC, DFC, 4, true><<<(NROI*DFC+255)/256, 256>>>(pPart, b1, pH1);

    fcmma_kernel<DFC, DFC, DFC, 3><<<dim3(DFC/BN, NROI/BM, 3), 128, GEMM_SMEM_BYTES>>>(pH1, w2, pPart);
    reduce_kernel<DFC, DFC, 3, true><<<(NROI*DFC+255)/256, 256>>>(pPart, b2, pH2);

    fcmma_kernel<DFC, M3, 192, 6><<<dim3(3, NROI/BM, 6), 128, GEMM_SMEM_BYTES>>>(pH2, w3, pPart);
    reduce_kernel<M3, 192, 6, false><<<(NROI*M3+255)/256, 256>>>(pPart, b3, pOM);

    // 4. deformable pool with offsets, times sigmoid mask -> out
    pool_kernel<true><<<NBIN, 256>>>(rois, out);
}

// round 5
// speedup vs baseline: 2.9632x; 1.0990x over previous
#include <cuda_runtime.h>
#include <math.h>
#include <stdint.h>

// ---------------- problem constants ----------------
#define NB 2
#define CC 256
#define HH 100
#define WW 100
#define NROI 512
#define PP 7
#define SS 4
#define SCALEF 0.0625f
#define TRANS_STDF 0.1f
#define K1 (CC*PP*PP)     // 12544
#define DFC 1024
#define M3 (PP*PP*3)      // 147
#define NBIN (NROI*PP*PP) // 25088

// ---------------- scratch (device globals; no allocs allowed) ----------------
__device__ float g_featT[NB*HH*WW*CC];   // NHWC features
__device__ float g_X[NROI*K1];           // pooled (no-trans) features
__device__ float g_H1[NROI*DFC];
__device__ float g_H2[NROI*DFC];
__device__ float g_OM[NROI*M3];          // offsets (2*49) + mask logit (49)
__device__ float g_part[8*NROI*DFC];     // split-K partials (16 MB, reused per layer)

// ======================= small PTX helpers (sm_80+ baseline only) =======================
__device__ __forceinline__ uint32_t smem_u32(const void* p) {
    uint32_t a;
    asm("{ .reg .u64 t; cvta.to.shared.u64 t, %1; cvt.u32.u64 %0, t; }"
        : "=r"(a) : "l"(p));
    return a;
}

__device__ __forceinline__ void cpasync16(uint32_t dst, const void* src, bool pred) {
    int sz = pred ? 16 : 0;
    asm volatile("cp.async.cg.shared.global [%0], [%1], 16, %2;"
                 :: "r"(dst), "l"(src), "r"(sz) : "memory");
}

__device__ __forceinline__ uint32_t f2tf32(float f) {
    uint32_t u;
    asm("cvt.rna.tf32.f32 %0, %1;" : "=r"(u) : "f"(f));
    return u;
}

__device__ __forceinline__ void mma_tf32(float c[4], const uint32_t a[4], const uint32_t b[2]) {
    asm volatile(
        "mma.sync.aligned.m16n8k8.row.col.f32.tf32.tf32.f32 "
        "{%0,%1,%2,%3}, {%4,%5,%6,%7}, {%8,%9}, {%0,%1,%2,%3};"
        : "+f"(c[0]), "+f"(c[1]), "+f"(c[2]), "+f"(c[3])
        : "r"(a[0]), "r"(a[1]), "r"(a[2]), "r"(a[3]), "r"(b[0]), "r"(b[1]));
}

// ---------------- NCHW -> NHWC transpose ----------------
__global__ void transpose_kernel(const float* __restrict__ feat) {
    __shared__ float tile[32][33];
    int b   = blockIdx.z;
    int hw0 = blockIdx.x * 32;
    int c0  = blockIdx.y * 32;
    int tx = threadIdx.x, ty = threadIdx.y; // (32, 8)
    const float* src = feat + (size_t)b * CC * HH * WW;
    float* dst = g_featT + (size_t)b * HH * WW * CC;
    #pragma unroll
    for (int j = 0; j < 32; j += 8) {
        int c  = c0 + ty + j;
        int hw = hw0 + tx;
        tile[ty + j][tx] = (hw < HH*WW) ? src[c * (HH*WW) + hw] : 0.0f;
    }
    __syncthreads();
    #pragma unroll
    for (int j = 0; j < 32; j += 8) {
        int hw = hw0 + ty + j;
        int c  = c0 + tx;
        if (hw < HH*WW) dst[hw * CC + c] = tile[tx][ty + j];
    }
}

// ---------------- deformable PSROI pool (group_size=1) ----------------
template<bool TRANS>
__global__ void pool_kernel(const float* __restrict__ rois, float* __restrict__ outp) {
    __shared__ float wgrid[36];
    __shared__ float s_cnt, s_mask;
    __shared__ int s_horg, s_worg, s_base;

    int bin = blockIdx.x;
    int n  = bin / 49;
    int pp = bin % 49;
    int tid = threadIdx.x;

    if (tid == 0) {
        #pragma unroll
        for (int i = 0; i < 36; i++) wgrid[i] = 0.0f;
        int ph = pp / 7, pw = pp % 7;
        const float* r = rois + n * 5;
        int b = (int)r[0];
        float rsw = rintf(r[1]) * SCALEF - 0.5f;
        float rsh = rintf(r[2]) * SCALEF - 0.5f;
        float rew = (rintf(r[3]) + 1.0f) * SCALEF - 0.5f;
        float reh = (rintf(r[4]) + 1.0f) * SCALEF - 0.5f;
        float roi_w = fmaxf(rew - rsw, 0.1f);
        float roi_h = fmaxf(reh - rsh, 0.1f);
        float bin_h = roi_h / (float)PP;
        float bin_w = roi_w / (float)PP;
        float sub_h = bin_h / (float)SS;
        float sub_w = bin_w / (float)SS;

        float tx_ = 0.0f, ty_ = 0.0f, mask = 1.0f;
        if (TRANS) {
            int part_h = (int)floorf((float)ph / (float)PP * 7.0f);
            int part_w = (int)floorf((float)pw / (float)PP * 7.0f);
            const float* o = g_OM + n * M3;
            tx_ = o[0*49 + part_h*7 + part_w] * TRANS_STDF;
            ty_ = o[1*49 + part_h*7 + part_w] * TRANS_STDF;
            float ml = o[2*49 + pp];
            mask = 1.0f / (1.0f + expf(-ml));
        }
        float hstart = (float)ph * bin_h + rsh + ty_ * roi_h;
        float wstart = (float)pw * bin_w + rsw + tx_ * roi_w;

        int horg = (int)floorf(fminf(fmaxf(hstart, 0.0f), (float)(HH-1)));
        int worg = (int)floorf(fminf(fmaxf(wstart, 0.0f), (float)(WW-1)));
        int cnt = 0;
        #pragma unroll
        for (int iy = 0; iy < SS; iy++) {
            float h = hstart + (float)iy * sub_h;
            #pragma unroll
            for (int ix = 0; ix < SS; ix++) {
                float w = wstart + (float)ix * sub_w;
                bool valid = (w >= -0.5f) && (w <= (float)WW - 0.5f) &&
                             (h >= -0.5f) && (h <= (float)HH - 0.5f);
                if (!valid) continue;
                cnt++;
                float hc = fminf(fmaxf(h, 0.0f), (float)(HH-1));
                float wc = fminf(fmaxf(w, 0.0f), (float)(WW-1));
                int h0 = (int)floorf(hc), w0 = (int)floorf(wc);
                int h1 = min(h0 + 1, HH - 1), w1 = min(w0 + 1, WW - 1);
                float lh = hc - (float)h0, lw = wc - (float)w0;
                int r0 = min(max(h0 - horg, 0), 5);
                int r1 = min(max(h1 - horg, 0), 5);
                int c0 = min(max(w0 - worg, 0), 5);
                int c1 = min(max(w1 - worg, 0), 5);
                wgrid[r0*6 + c0] += (1.0f - lh) * (1.0f - lw);
                wgrid[r0*6 + c1] += (1.0f - lh) * lw;
                wgrid[r1*6 + c0] += lh * (1.0f - lw);
                wgrid[r1*6 + c1] += lh * lw;
            }
        }
        s_cnt  = (float)cnt;
        s_mask = mask;
        s_horg = horg; s_worg = worg;
        s_base = b * HH * WW * CC;
    }
    __syncthreads();

    int c = tid;               // 256 threads == CC channels
    int base = s_base;
    int horg = s_horg, worg = s_worg;
    float acc = 0.0f;
    #pragma unroll
    for (int cell = 0; cell < 36; cell++) {
        float wt = wgrid[cell];
        if (wt != 0.0f) {
            int y = min(horg + cell / 6, HH - 1);
            int x = min(worg + cell % 6, WW - 1);
            acc += wt * g_featT[base + (y * WW + x) * CC + c];
        }
    }
    float cnt = s_cnt;
    float v = (cnt > 0.0f) ? (acc / cnt) : 0.0f;
    if (TRANS) {
        outp[(size_t)n * K1 + c * 49 + pp] = v * s_mask;
    } else {
        g_X[(size_t)n * K1 + c * 49 + pp] = v;
    }
}

// ============ TF32 mma.sync GEMM with split-K, 128x128 tile ============
// BM=BN=128, BK=32, 4 warps (64x64 warp tiles), 3-stage cp.async pipeline.
#define BM 128
#define BN 128
#define BK 32
#define GPAD 36
#define GSTAGES 3
#define ASZ (BM*GPAD)
#define BSZ (BN*GPAD)
#define STGSZ (ASZ+BSZ)
#define GEMM_SMEM_BYTES (GSTAGES*STGSZ*4)

template<int KDIM, int JROWS, int JS, int SPLITK>
__global__ void __launch_bounds__(128) fcmma_kernel(
    const float* __restrict__ A, const float* __restrict__ Wt,
    float* __restrict__ Part)
{
    static_assert(KDIM % BK == 0, "K multiple of BK");
    constexpr int KT = KDIM / BK;
    constexpr int CH = (KT + SPLITK - 1) / SPLITK;

    extern __shared__ float sm[];
    int tid  = threadIdx.x;
    int lane = tid & 31, wid = tid >> 5;
    int m0 = blockIdx.y * BM, n0 = blockIdx.x * BN;
    int z  = blockIdx.z;
    int t0 = z * CH;
    int ntc = min(KT - t0, CH);

    int g = lane >> 2, tg = lane & 3;
    int wm = (wid & 1) * 64, wn = (wid >> 1) * 64;

    float c[4][8][4];
    #pragma unroll
    for (int mt = 0; mt < 4; mt++)
        #pragma unroll
        for (int nt = 0; nt < 8; nt++)
            #pragma unroll
            for (int q = 0; q < 4; q++) c[mt][nt][q] = 0.0f;

    int lrow = tid >> 3;     // 0..15
    int lchk = tid & 7;      // 0..7 (16B chunks of a 128B = BK row)

    auto load_stage = [&](int s, int t) {
        float* As = sm + s * STGSZ;
        float* Bs = As + ASZ;
        int kg = t * BK + lchk * 4;
        #pragma unroll
        for (int it = 0; it < 8; it++) {
            int r = lrow + it * 16;
            cpasync16(smem_u32(As + r * GPAD + lchk * 4),
                      A + (size_t)(m0 + r) * KDIM + kg, true);
            int br = n0 + r;
            bool ok = ((JROWS % BN) == 0) || (br < JROWS);
            cpasync16(smem_u32(Bs + r * GPAD + lchk * 4),
                      Wt + (size_t)(ok ? br : 0) * KDIM + kg, ok);
        }
    };

    #pragma unroll
    for (int s = 0; s < GSTAGES - 1; s++) {
        if (s < ntc) load_stage(s, t0 + s);
        asm volatile("cp.async.commit_group;" ::: "memory");
    }

    #pragma unroll 1
    for (int i = 0; i < ntc; i++) {
        asm volatile("cp.async.wait_group %0;" :: "n"(GSTAGES - 2) : "memory");
        __syncthreads();

        int tn = i + GSTAGES - 1;
        if (tn < ntc) load_stage(tn % GSTAGES, t0 + tn);
        asm volatile("cp.async.commit_group;" ::: "memory");

        const float* As = sm + (i % GSTAGES) * STGSZ;
        const float* Bs = As + ASZ;
        #pragma unroll
        for (int ks = 0; ks < 4; ks++) {
            int kk = ks * 8;
            uint32_t a[4][4], b[8][2];
            #pragma unroll
            for (int mt = 0; mt < 4; mt++) {
                int m = wm + mt * 16 + g;
                a[mt][0] = f2tf32(As[m * GPAD + kk + tg]);
                a[mt][1] = f2tf32(As[(m + 8) * GPAD + kk + tg]);
                a[mt][2] = f2tf32(As[m * GPAD + kk + tg + 4]);
                a[mt][3] = f2tf32(As[(m + 8) * GPAD + kk + tg + 4]);
            }
            #pragma unroll
            for (int nt = 0; nt < 8; nt++) {
                int nn = wn + nt * 8 + g;
                b[nt][0] = f2tf32(Bs[nn * GPAD + kk + tg]);
                b[nt][1] = f2tf32(Bs[nn * GPAD + kk + tg + 4]);
            }
            #pragma unroll
            for (int mt = 0; mt < 4; mt++)
                #pragma unroll
                for (int nt = 0; nt < 8; nt++)
                    mma_tf32(c[mt][nt], a[mt], b[nt]);
        }
        __syncthreads();
    }

    // write partials
    float* P = Part + (size_t)z * NROI * JS;
    #pragma unroll
    for (int mt = 0; mt < 4; mt++) {
        int row0 = m0 + wm + mt * 16 + g;
        #pragma unroll
        for (int nt = 0; nt < 8; nt++) {
            int j0 = n0 + wn + nt * 8 + tg * 2;
            #pragma unroll
            for (int h = 0; h < 2; h++) {
                int row = row0 + h * 8;
                float2 v = make_float2(c[mt][nt][h*2], c[mt][nt][h*2+1]);
                *reinterpret_cast<float2*>(P + (size_t)row * JS + j0) = v;
            }
        }
    }
}

template<int J, int JS, int SPLITK, bool RELU>
__global__ void __launch_bounds__(256) reduce_kernel(
    const float* __restrict__ Part, const float* __restrict__ bias,
    float* __restrict__ Cout)
{
    int idx = blockIdx.x * 256 + threadIdx.x;
    if (idx >= NROI * J) return;
    int row = idx / J, j = idx - row * J;
    float v = 0.0f;
    #pragma unroll
    for (int z = 0; z < SPLITK; z++)
        v += Part[((size_t)z * NROI + row) * JS + j];
    v += __ldg(bias + j);
    if (RELU) v = fmaxf(v, 0.0f);
    Cout[idx] = v;
}

// ======================= launch =======================
extern "C" void kernel_launch(void* const* d_in, const int* in_sizes, int n_in,
                              void* d_out, int out_size) {
    const float* feat = (const float*)d_in[0];
    const float* rois = (const float*)d_in[1];
    const float* w1   = (const float*)d_in[2];
    const float* b1   = (const float*)d_in[3];
    const float* w2   = (const float*)d_in[4];
    const float* b2   = (const float*)d_in[5];
    const float* w3   = (const float*)d_in[6];
    const float* b3   = (const float*)d_in[7];
    float* out = (float*)d_out;

    static float *pX=nullptr, *pH1=nullptr, *pH2=nullptr, *pOM=nullptr, *pPart=nullptr;
    if (!pX) {
        void* p;
        cudaGetSymbolAddress(&p, g_X);    pX    = (float*)p;
        cudaGetSymbolAddress(&p, g_H1);   pH1   = (float*)p;
        cudaGetSymbolAddress(&p, g_H2);   pH2   = (float*)p;
        cudaGetSymbolAddress(&p, g_OM);   pOM   = (float*)p;
        cudaGetSymbolAddress(&p, g_part); pPart = (float*)p;
        cudaFuncSetAttribute(fcmma_kernel<K1,  DFC, DFC, 8>,
                             cudaFuncAttributeMaxDynamicSharedMemorySize, GEMM_SMEM_BYTES);
        cudaFuncSetAttribute(fcmma_kernel<DFC, DFC, DFC, 8>,
                             cudaFuncAttributeMaxDynamicSharedMemorySize, GEMM_SMEM_BYTES);
        cudaFuncSetAttribute(fcmma_kernel<DFC, M3,  256, 16>,
                             cudaFuncAttributeMaxDynamicSharedMemorySize, GEMM_SMEM_BYTES);
    }

    // 1. NCHW -> NHWC
    dim3 tb(32, 8);
    dim3 tg((HH*WW + 31) / 32, CC / 32, NB);
    transpose_kernel<<<tg, tb>>>(feat);

    // 2. pool without offsets -> g_X
    pool_kernel<false><<<NBIN, 256>>>(rois, nullptr);

    // 3. FC stack: split-K TF32 mma.sync (128x128 tiles) + reduce
    fcmma_kernel<K1,  DFC, DFC, 8><<<dim3(DFC/BN, NROI/BM, 8), 128, GEMM_SMEM_BYTES>>>(pX,  w1, pPart);
    reduce_kernel<DFC, DFC, 8, true><<<(NROI*DFC+255)/256, 256>>>(pPart, b1, pH1);

    fcmma_kernel<DFC, DFC, DFC, 8><<<dim3(DFC/BN, NROI/BM, 8), 128, GEMM_SMEM_BYTES>>>(pH1, w2, pPart);
    reduce_kernel<DFC, DFC, 8, true><<<(NROI*DFC+255)/256, 256>>>(pPart, b2, pH2);

    fcmma_kernel<DFC, M3, 256, 16><<<dim3(2, NROI/BM, 16), 128, GEMM_SMEM_BYTES>>>(pH2, w3, pPart);
    reduce_kernel<M3, 256, 16, false><<<(NROI*M3+255)/256, 256>>>(pPart, b3, pOM);

    // 4. deformable pool with offsets, times sigmoid mask -> out
    pool_kernel<true><<<NBIN, 256>>>(rois, out);
}

// round 6
// speedup vs baseline: 3.3256x; 1.1223x over previous
#include <cuda_runtime.h>
#include <math.h>
#include <stdint.h>

// ---------------- problem constants ----------------
#define NB 2
#define CC 256
#define HH 100
#define WW 100
#define NROI 512
#define PP 7
#define SS 4
#define SCALEF 0.0625f
#define TRANS_STDF 0.1f
#define K1 (CC*PP*PP)     // 12544
#define DFC 1024
#define M3 (PP*PP*3)      // 147
#define NBIN (NROI*PP*PP) // 25088
#define META_W 44

// ---------------- scratch (device globals; no allocs allowed) ----------------
__device__ float g_featT[NB*HH*WW*CC];   // NHWC features
__device__ float g_X[NROI*K1];           // pooled (no-trans) features (tf32-rounded)
__device__ float g_H1[NROI*DFC];
__device__ float g_H2[NROI*DFC];
__device__ float g_OM[NROI*M3];          // offsets (2*49) + mask logit (49)
__device__ float g_part[8*NROI*DFC];     // split-K partials (16 MB)
__device__ float g_meta[NBIN*META_W];    // per-bin pooling metadata

// ======================= small PTX helpers (sm_80+ baseline only) =======================
__device__ __forceinline__ uint32_t smem_u32(const void* p) {
    uint32_t a;
    asm("{ .reg .u64 t; cvta.to.shared.u64 t, %1; cvt.u32.u64 %0, t; }"
        : "=r"(a) : "l"(p));
    return a;
}

__device__ __forceinline__ void cpasync16(uint32_t dst, const void* src, bool pred) {
    int sz = pred ? 16 : 0;
    asm volatile("cp.async.cg.shared.global [%0], [%1], 16, %2;"
                 :: "r"(dst), "l"(src), "r"(sz) : "memory");
}

__device__ __forceinline__ uint32_t f2tf32(float f) {
    uint32_t u;
    asm("cvt.rna.tf32.f32 %0, %1;" : "=r"(u) : "f"(f));
    return u;
}

__device__ __forceinline__ float roundtf32(float f) {
    return __uint_as_float(f2tf32(f));
}

__device__ __forceinline__ void mma_tf32(float c[4], const uint32_t a[4], const uint32_t b[2]) {
    asm volatile(
        "mma.sync.aligned.m16n8k8.row.col.f32.tf32.tf32.f32 "
        "{%0,%1,%2,%3}, {%4,%5,%6,%7}, {%8,%9}, {%0,%1,%2,%3};"
        : "+f"(c[0]), "+f"(c[1]), "+f"(c[2]), "+f"(c[3])
        : "r"(a[0]), "r"(a[1]), "r"(a[2]), "r"(a[3]), "r"(b[0]), "r"(b[1]));
}

// ---------------- NCHW -> NHWC transpose ----------------
__global__ void transpose_kernel(const float* __restrict__ feat) {
    __shared__ float tile[32][33];
    int b   = blockIdx.z;
    int hw0 = blockIdx.x * 32;
    int c0  = blockIdx.y * 32;
    int tx = threadIdx.x, ty = threadIdx.y; // (32, 8)
    const float* src = feat + (size_t)b * CC * HH * WW;
    float* dst = g_featT + (size_t)b * HH * WW * CC;
    #pragma unroll
    for (int j = 0; j < 32; j += 8) {
        int c  = c0 + ty + j;
        int hw = hw0 + tx;
        tile[ty + j][tx] = (hw < HH*WW) ? src[c * (HH*WW) + hw] : 0.0f;
    }
    __syncthreads();
    #pragma unroll
    for (int j = 0; j < 32; j += 8) {
        int hw = hw0 + ty + j;
        int c  = c0 + tx;
        if (hw < HH*WW) dst[hw * CC + c] = tile[tx][ty + j];
    }
}

// ---------------- pool metadata: one thread per bin ----------------
template<bool TRANS>
__global__ void __launch_bounds__(256) pool_meta_kernel(const float* __restrict__ rois) {
    __shared__ float swg[256 * 36];
    int tid = threadIdx.x;
    int bin = blockIdx.x * 256 + tid;
    if (bin >= NBIN) return;
    float* wg = swg + tid * 36;
    #pragma unroll
    for (int i = 0; i < 36; i++) wg[i] = 0.0f;

    int n  = bin / 49;
    int pp = bin % 49;
    int ph = pp / 7, pw = pp % 7;
    const float* r = rois + n * 5;
    int b = (int)r[0];
    float rsw = rintf(r[1]) * SCALEF - 0.5f;
    float rsh = rintf(r[2]) * SCALEF - 0.5f;
    float rew = (rintf(r[3]) + 1.0f) * SCALEF - 0.5f;
    float reh = (rintf(r[4]) + 1.0f) * SCALEF - 0.5f;
    float roi_w = fmaxf(rew - rsw, 0.1f);
    float roi_h = fmaxf(reh - rsh, 0.1f);
    float bin_h = roi_h / (float)PP;
    float bin_w = roi_w / (float)PP;
    float sub_h = bin_h / (float)SS;
    float sub_w = bin_w / (float)SS;

    float tx_ = 0.0f, ty_ = 0.0f, mask = 1.0f;
    if (TRANS) {
        int part_h = (int)floorf((float)ph / (float)PP * 7.0f);
        int part_w = (int)floorf((float)pw / (float)PP * 7.0f);
        const float* o = g_OM + n * M3;
        tx_ = o[0*49 + part_h*7 + part_w] * TRANS_STDF;
        ty_ = o[1*49 + part_h*7 + part_w] * TRANS_STDF;
        float ml = o[2*49 + pp];
        mask = 1.0f / (1.0f + expf(-ml));
    }
    float hstart = (float)ph * bin_h + rsh + ty_ * roi_h;
    float wstart = (float)pw * bin_w + rsw + tx_ * roi_w;

    int horg = (int)floorf(fminf(fmaxf(hstart, 0.0f), (float)(HH-1)));
    int worg = (int)floorf(fminf(fmaxf(wstart, 0.0f), (float)(WW-1)));
    int cnt = 0;
    #pragma unroll
    for (int iy = 0; iy < SS; iy++) {
        float h = hstart + (float)iy * sub_h;
        #pragma unroll
        for (int ix = 0; ix < SS; ix++) {
            float w = wstart + (float)ix * sub_w;
            bool valid = (w >= -0.5f) && (w <= (float)WW - 0.5f) &&
                         (h >= -0.5f) && (h <= (float)HH - 0.5f);
            if (!valid) continue;
            cnt++;
            float hc = fminf(fmaxf(h, 0.0f), (float)(HH-1));
            float wc = fminf(fmaxf(w, 0.0f), (float)(WW-1));
            int h0 = (int)floorf(hc), w0 = (int)floorf(wc);
            int h1 = min(h0 + 1, HH - 1), w1 = min(w0 + 1, WW - 1);
            float lh = hc - (float)h0, lw = wc - (float)w0;
            int r0 = min(max(h0 - horg, 0), 5);
            int r1 = min(max(h1 - horg, 0), 5);
            int c0 = min(max(w0 - worg, 0), 5);
            int c1 = min(max(w1 - worg, 0), 5);
            wg[r0*6 + c0] += (1.0f - lh) * (1.0f - lw);
            wg[r0*6 + c1] += (1.0f - lh) * lw;
            wg[r1*6 + c0] += lh * (1.0f - lw);
            wg[r1*6 + c1] += lh * lw;
        }
    }
    float* m = g_meta + (size_t)bin * META_W;
    #pragma unroll
    for (int i = 0; i < 36; i++) m[i] = wg[i];
    m[36] = (float)cnt;
    m[37] = mask;
    m[38] = __int_as_float(horg);
    m[39] = __int_as_float(worg);
    m[40] = __int_as_float(b * HH * WW * CC);
}

// ---------------- pool gather: one block per bin, 256 threads = channels ----------------
template<bool TRANS>
__global__ void __launch_bounds__(256) pool_gather_kernel(float* __restrict__ outp) {
    __shared__ float meta[41];
    int bin = blockIdx.x;
    int tid = threadIdx.x;
    if (tid < 41) meta[tid] = g_meta[(size_t)bin * META_W + tid];
    __syncthreads();

    int horg = __float_as_int(meta[38]);
    int worg = __float_as_int(meta[39]);
    int base = __float_as_int(meta[40]);
    int c = tid;
    float acc = 0.0f;
    #pragma unroll
    for (int cell = 0; cell < 36; cell++) {
        float wt = meta[cell];
        if (wt != 0.0f) {
            int y = min(horg + cell / 6, HH - 1);
            int x = min(worg + cell % 6, WW - 1);
            acc += wt * g_featT[base + (y * WW + x) * CC + c];
        }
    }
    float cnt = meta[36];
    float v = (cnt > 0.0f) ? (acc / cnt) : 0.0f;
    int n  = bin / 49;
    int pp = bin % 49;
    if (TRANS) {
        outp[(size_t)n * K1 + c * 49 + pp] = v * meta[37];
    } else {
        g_X[(size_t)n * K1 + c * 49 + pp] = roundtf32(v);   // pre-round for GEMM A
    }
}

// ============ TF32 mma.sync GEMM with split-K, 128x128 tile, 8 warps ============
// Warp tile 64x32 (2 M-warps x 4 N-warps), BK=32, 3-stage cp.async pipeline.
// A is pre-rounded to tf32 by its producer -> raw-bit frags; B converted in-loop.
#define BM 128
#define BN 128
#define BK 32
#define GPAD 36
#define GSTAGES 3
#define ASZ (BM*GPAD)
#define BSZ (BN*GPAD)
#define STGSZ (ASZ+BSZ)
#define GEMM_SMEM_BYTES (GSTAGES*STGSZ*4)

template<int KDIM, int JROWS, int JS, int SPLITK>
__global__ void __launch_bounds__(256, 1) fcmma_kernel(
    const float* __restrict__ A, const float* __restrict__ Wt,
    float* __restrict__ Part)
{
    static_assert(KDIM % BK == 0, "K multiple of BK");
    constexpr int KT = KDIM / BK;
    constexpr int CH = (KT + SPLITK - 1) / SPLITK;

    extern __shared__ float sm[];
    int tid  = threadIdx.x;
    int lane = tid & 31, wid = tid >> 5;
    int m0 = blockIdx.y * BM, n0 = blockIdx.x * BN;
    int z  = blockIdx.z;
    int t0 = z * CH;
    int ntc = min(KT - t0, CH);

    int g = lane >> 2, tg = lane & 3;
    int wm = (wid & 1) * 64;        // 2 warps along M
    int wn = (wid >> 1) * 32;       // 4 warps along N

    float c[4][4][4];
    #pragma unroll
    for (int mt = 0; mt < 4; mt++)
        #pragma unroll
        for (int nt = 0; nt < 4; nt++)
            #pragma unroll
            for (int q = 0; q < 4; q++) c[mt][nt][q] = 0.0f;

    int lrow = tid >> 3;     // 0..31
    int lchk = tid & 7;      // 0..7 (16B chunks of a BK row)

    auto load_stage = [&](int s, int t) {
        float* As = sm + s * STGSZ;
        float* Bs = As + ASZ;
        int kg = t * BK + lchk * 4;
        #pragma unroll
        for (int it = 0; it < 4; it++) {
            int r = lrow + it * 32;
            cpasync16(smem_u32(As + r * GPAD + lchk * 4),
                      A + (size_t)(m0 + r) * KDIM + kg, true);
            int br = n0 + r;
            bool ok = ((JROWS % BN) == 0) || (br < JROWS);
            cpasync16(smem_u32(Bs + r * GPAD + lchk * 4),
                      Wt + (size_t)(ok ? br : 0) * KDIM + kg, ok);
        }
    };

    #pragma unroll
    for (int s = 0; s < GSTAGES - 1; s++) {
        if (s < ntc) load_stage(s, t0 + s);
        asm volatile("cp.async.commit_group;" ::: "memory");
    }

    #pragma unroll 1
    for (int i = 0; i < ntc; i++) {
        asm volatile("cp.async.wait_group %0;" :: "n"(GSTAGES - 2) : "memory");
        __syncthreads();

        int tn = i + GSTAGES - 1;
        if (tn < ntc) load_stage(tn % GSTAGES, t0 + tn);
        asm volatile("cp.async.commit_group;" ::: "memory");

        const float* As = sm + (i % GSTAGES) * STGSZ;
        const float* Bs = As + ASZ;
        #pragma unroll
        for (int ks = 0; ks < 4; ks++) {
            int kk = ks * 8;
            uint32_t a[4][4], b[4][2];
            #pragma unroll
            for (int mt = 0; mt < 4; mt++) {
                int m = wm + mt * 16 + g;
                a[mt][0] = __float_as_uint(As[m * GPAD + kk + tg]);
                a[mt][1] = __float_as_uint(As[(m + 8) * GPAD + kk + tg]);
                a[mt][2] = __float_as_uint(As[m * GPAD + kk + tg + 4]);
                a[mt][3] = __float_as_uint(As[(m + 8) * GPAD + kk + tg + 4]);
            }
            #pragma unroll
            for (int nt = 0; nt < 4; nt++) {
                int nn = wn + nt * 8 + g;
                b[nt][0] = f2tf32(Bs[nn * GPAD + kk + tg]);
                b[nt][1] = f2tf32(Bs[nn * GPAD + kk + tg + 4]);
            }
            #pragma unroll
            for (int mt = 0; mt < 4; mt++)
                #pragma unroll
                for (int nt = 0; nt < 4; nt++)
                    mma_tf32(c[mt][nt], a[mt], b[nt]);
        }
        __syncthreads();
    }

    // write partials
    float* P = Part + (size_t)z * NROI * JS;
    #pragma unroll
    for (int mt = 0; mt < 4; mt++) {
        int row0 = m0 + wm + mt * 16 + g;
        #pragma unroll
        for (int nt = 0; nt < 4; nt++) {
            int j0 = n0 + wn + nt * 8 + tg * 2;
            #pragma unroll
            for (int h = 0; h < 2; h++) {
                int row = row0 + h * 8;
                float2 v = make_float2(c[mt][nt][h*2], c[mt][nt][h*2+1]);
                *reinterpret_cast<float2*>(P + (size_t)row * JS + j0) = v;
            }
        }
    }
}

// vectorized reduce (J % 4 == 0): partials + bias + relu (+ tf32 round for next GEMM)
template<int J, int JS, int SPLITK, bool RELU, bool ROUND>
__global__ void __launch_bounds__(256) reduce_vec_kernel(
    const float* __restrict__ Part, const float* __restrict__ bias,
    float* __restrict__ Cout)
{
    int idx = blockIdx.x * 256 + threadIdx.x;
    if (idx >= NROI * (J / 4)) return;
    int row = idx / (J / 4), jv = idx - row * (J / 4);
    int j = jv * 4;
    float4 v = make_float4(0.f, 0.f, 0.f, 0.f);
    #pragma unroll
    for (int z = 0; z < SPLITK; z++) {
        float4 p = *reinterpret_cast<const float4*>(Part + ((size_t)z * NROI + row) * JS + j);
        v.x += p.x; v.y += p.y; v.z += p.z; v.w += p.w;
    }
    float4 bb = *reinterpret_cast<const float4*>(bias + j);
    v.x += bb.x; v.y += bb.y; v.z += bb.z; v.w += bb.w;
    if (RELU) {
        v.x = fmaxf(v.x, 0.f); v.y = fmaxf(v.y, 0.f);
        v.z = fmaxf(v.z, 0.f); v.w = fmaxf(v.w, 0.f);
    }
    if (ROUND) {
        v.x = roundtf32(v.x); v.y = roundtf32(v.y);
        v.z = roundtf32(v.z); v.w = roundtf32(v.w);
    }
    *reinterpret_cast<float4*>(Cout + (size_t)row * J + j) = v;
}

template<int J, int JS, int SPLITK, bool RELU>
__global__ void __launch_bounds__(256) reduce_kernel(
    const float* __restrict__ Part, const float* __restrict__ bias,
    float* __restrict__ Cout)
{
    int idx = blockIdx.x * 256 + threadIdx.x;
    if (idx >= NROI * J) return;
    int row = idx / J, j = idx - row * J;
    float v = 0.0f;
    #pragma unroll
    for (int z = 0; z < SPLITK; z++)
        v += Part[((size_t)z * NROI + row) * JS + j];
    v += __ldg(bias + j);
    if (RELU) v = fmaxf(v, 0.0f);
    Cout[idx] = v;
}

// ======================= launch =======================
extern "C" void kernel_launch(void* const* d_in, const int* in_sizes, int n_in,
                              void* d_out, int out_size) {
    const float* feat = (const float*)d_in[0];
    const float* rois = (const float*)d_in[1];
    const float* w1   = (const float*)d_in[2];
    const float* b1   = (const float*)d_in[3];
    const float* w2   = (const float*)d_in[4];
    const float* b2   = (const float*)d_in[5];
    const float* w3   = (const float*)d_in[6];
    const float* b3   = (const float*)d_in[7];
    float* out = (float*)d_out;

    static float *pX=nullptr, *pH1=nullptr, *pH2=nullptr, *pOM=nullptr, *pPart=nullptr;
    if (!pX) {
        void* p;
        cudaGetSymbolAddress(&p, g_X);    pX    = (float*)p;
        cudaGetSymbolAddress(&p, g_H1);   pH1   = (float*)p;
        cudaGetSymbolAddress(&p, g_H2);   pH2   = (float*)p;
        cudaGetSymbolAddress(&p, g_OM);   pOM   = (float*)p;
        cudaGetSymbolAddress(&p, g_part); pPart = (float*)p;
        cudaFuncSetAttribute(fcmma_kernel<K1,  DFC, DFC, 8>,
                             cudaFuncAttributeMaxDynamicSharedMemorySize, GEMM_SMEM_BYTES);
        cudaFuncSetAttribute(fcmma_kernel<DFC, DFC, DFC, 8>,
                             cudaFuncAttributeMaxDynamicSharedMemorySize, GEMM_SMEM_BYTES);
        cudaFuncSetAttribute(fcmma_kernel<DFC, M3,  256, 16>,
                             cudaFuncAttributeMaxDynamicSharedMemorySize, GEMM_SMEM_BYTES);
    }

    // 1. NCHW -> NHWC
    dim3 tb(32, 8);
    dim3 tg((HH*WW + 31) / 32, CC / 32, NB);
    transpose_kernel<<<tg, tb>>>(feat);

    // 2. pool (no offsets) -> g_X (tf32-rounded)
    pool_meta_kernel<false><<<(NBIN + 255) / 256, 256>>>(rois);
    pool_gather_kernel<false><<<NBIN, 256>>>(nullptr);

    // 3. FC stack: split-K TF32 mma.sync (128x128, 8 warps) + fused reduce
    fcmma_kernel<K1,  DFC, DFC, 8><<<dim3(DFC/BN, NROI/BM, 8), 256, GEMM_SMEM_BYTES>>>(pX,  w1, pPart);
    reduce_vec_kernel<DFC, DFC, 8, true, true><<<(NROI*DFC/4 + 255)/256, 256>>>(pPart, b1, pH1);

    fcmma_kernel<DFC, DFC, DFC, 8><<<dim3(DFC/BN, NROI/BM, 8), 256, GEMM_SMEM_BYTES>>>(pH1, w2, pPart);
    reduce_vec_kernel<DFC, DFC, 8, true, true><<<(NROI*DFC/4 + 255)/256, 256>>>(pPart, b2, pH2);

    fcmma_kernel<DFC, M3, 256, 16><<<dim3(2, NROI/BM, 16), 256, GEMM_SMEM_BYTES>>>(pH2, w3, pPart);
    reduce_kernel<M3, 256, 16, false><<<(NROI*M3 + 255)/256, 256>>>(pPart, b3, pOM);

    // 4. deformable pool with offsets, times sigmoid mask -> out
    pool_meta_kernel<true><<<(NBIN + 255) / 256, 256>>>(rois);
    pool_gather_kernel<true><<<NBIN, 256>>>(out);
}